// round 2
// baseline (speedup 1.0000x reference)
#include <cuda_runtime.h>
#include <cstdint>

// CachedMPS on GB300: normalization-free MPS chain, fp32 via packed f32x2 FMA.
//
// Algebra: per-step L2-normalize is a pure positive rescale of a homogeneous
// linear map -> drop it; rescale every 32 steps (range control only); the
// FINAL normalization must be eps-free (reference's M ends at norm ~1, where
// eps is negligible; our M ends at ~4e-8 where eps would inject ~20% scale
// error -- that was R1's 0.338 failure).

#define DEV_INLINE __device__ __forceinline__

static constexpr int D    = 32;
static constexpr int L    = 256;
static constexpr int NMID = 254;   // L - 2
static constexpr int C    = 10;
static constexpr int TPB  = 128;
static constexpr float HALF_PI = 1.57079632679489662f;  // rounds to 0x3FC90FDB

// ---------------- f32x2 helpers (sm_103a packed fp32) ----------------
DEV_INLINE unsigned long long pack2(float x) {
    unsigned long long r;
    asm("mov.b64 %0, {%1, %1};" : "=l"(r) : "f"(x));
    return r;
}
DEV_INLINE void unpack2(unsigned long long v, float& lo, float& hi) {
    asm("mov.b64 {%0, %1}, %2;" : "=f"(lo), "=f"(hi) : "l"(v));
}
DEV_INLINE void ffma2(unsigned long long& d, unsigned long long a, unsigned long long b) {
    // d = a * b + d   (two fp32 lanes)
    asm("fma.rn.f32x2 %0, %1, %2, %0;" : "+l"(d) : "l"(a), "l"(b));
}

// ---------------- cp.async 16B ----------------
DEV_INLINE void cp16(unsigned dst_smem, const void* src) {
    asm volatile("cp.async.cg.shared.global [%0], [%1], 16;"
                 :: "r"(dst_smem), "l"(src));
}
DEV_INLINE void cp_commit() { asm volatile("cp.async.commit_group;"); }
DEV_INLINE void cp_wait0()  { asm volatile("cp.async.wait_group 0;" ::: "memory"); }

// Shared: double-buffered step tile.  Each step tile = A0[32][32] + A1[32][32]
// = 2048 floats = 1024 ull = 8KB.
__global__ void __launch_bounds__(TPB)
mps_chain_kernel(const float* __restrict__ x,
                 const float* __restrict__ core0,
                 const float* __restrict__ cores_mid,
                 const float* __restrict__ coreN,
                 float* __restrict__ out,
                 int B)
{
    __shared__ __align__(16) unsigned long long sA[2][1024];  // 16KB

    const int tid = threadIdx.x;
    const int b   = blockIdx.x * TPB + tid;
    const bool active = (b < B);
    const int brow = active ? b : 0;   // keep loads in-bounds for inactive threads

    // ---- prefetch step 0 tile (512 x 16B) ----
    unsigned sbase0 = (unsigned)__cvta_generic_to_shared(&sA[0][0]);
    unsigned sbase1 = (unsigned)__cvta_generic_to_shared(&sA[1][0]);
    {
        const float* g = cores_mid;  // step 0 at offset 0
        #pragma unroll
        for (int i = 0; i < 4; i++) {
            int idx = tid + i * TPB;          // 0..511
            cp16(sbase0 + idx * 16, g + idx * 4);
        }
        cp_commit();
    }

    const float* xr = x + (size_t)brow * L;

    // ---- init M0 = c0 * core0[0,:] + s0 * core0[1,:]  (core0 is [F,1,D]) ----
    float m[D];
    {
        float s0, c0;
        __sincosf(HALF_PI * xr[0], &s0, &c0);
        #pragma unroll
        for (int d = 0; d < D; d++)
            m[d] = c0 * core0[d] + s0 * core0[D + d];
    }

    cp_wait0();
    __syncthreads();

    // ---- main sequential chain ----
    for (int l = 0; l < NMID; l++) {
        const int cur = l & 1;

        // prefetch next step tile into the other buffer
        if (l + 1 < NMID) {
            const float* g = cores_mid + (size_t)(l + 1) * 2048;
            unsigned sb = (cur == 0) ? sbase1 : sbase0;
            #pragma unroll
            for (int i = 0; i < 4; i++) {
                int idx = tid + i * TPB;
                cp16(sb + idx * 16, g + idx * 4);
            }
            cp_commit();
        }

        float sv, cv;
        __sincosf(HALF_PI * xr[l + 1], &sv, &cv);

        unsigned long long acc[16];
        #pragma unroll
        for (int j = 0; j < 16; j++) acc[j] = 0ull;   // (0.f, 0.f)

        const unsigned long long* A0 = &sA[cur][0];
        const unsigned long long* A1 = &sA[cur][512];

        #pragma unroll
        for (int a = 0; a < D; a++) {
            const float ma = m[a];
            const unsigned long long cm = pack2(cv * ma);
            const unsigned long long sm = pack2(sv * ma);
            const ulonglong2* r0 = reinterpret_cast<const ulonglong2*>(A0 + a * 16);
            const ulonglong2* r1 = reinterpret_cast<const ulonglong2*>(A1 + a * 16);
            #pragma unroll
            for (int q = 0; q < 8; q++) {
                ulonglong2 v0 = r0[q];             // LDS.128 (broadcast)
                ffma2(acc[2 * q],     cm, v0.x);
                ffma2(acc[2 * q + 1], cm, v0.y);
                ulonglong2 v1 = r1[q];
                ffma2(acc[2 * q],     sm, v1.x);
                ffma2(acc[2 * q + 1], sm, v1.y);
            }
        }

        #pragma unroll
        for (int j = 0; j < 16; j++)
            unpack2(acc[j], m[2 * j], m[2 * j + 1]);

        // range control (any positive rescale is mathematically invisible)
        if ((l & 31) == 31) {
            float ss = 0.f;
            #pragma unroll
            for (int d = 0; d < D; d++) ss += m[d] * m[d];
            const float r = rsqrtf(ss);
            #pragma unroll
            for (int d = 0; d < D; d++) m[d] *= r;
        }

        cp_wait0();
        __syncthreads();
    }

    // ---- readout ----
    // Reference's final M is unit-norm up to O(1e-8); ours differs only by a
    // positive scalar, so the exact final op is a PURE unit-normalize (NO eps:
    // our ||m|| ~ 4e-8 here, eps would inject ~20% scale error).
    if (active) {
        float ss = 0.f;
        #pragma unroll
        for (int d = 0; d < D; d++) ss += m[d] * m[d];
        const float inv = rsqrtf(ss);

        float sL, cL;
        __sincosf(HALF_PI * xr[L - 1], &sL, &cL);

        float lg[C];
        #pragma unroll
        for (int c = 0; c < C; c++) lg[c] = 0.f;

        #pragma unroll
        for (int a = 0; a < D; a++) {
            const float ma = m[a];
            #pragma unroll
            for (int c = 0; c < C; c++) {
                // coreN is [F, D, C]
                const float w = cL * coreN[a * C + c] + sL * coreN[D * C + a * C + c];
                lg[c] += ma * w;
            }
        }
        #pragma unroll
        for (int c = 0; c < C; c++)
            out[(size_t)b * C + c] = lg[c] * inv;
    }
}

extern "C" void kernel_launch(void* const* d_in, const int* in_sizes, int n_in,
                              void* d_out, int out_size)
{
    // metadata order: x [B,L] f32, core0 [F,1,D] f32, cores_mid [L-2,F,D,D] f32,
    //                 coreN [F,D,C] f32 -> out [B,C] f32
    const float* x         = (const float*)d_in[0];
    const float* core0     = (const float*)d_in[1];
    const float* cores_mid = (const float*)d_in[2];
    const float* coreN     = (const float*)d_in[3];
    float* out = (float*)d_out;

    const int B = in_sizes[0] / L;
    const int grid = (B + TPB - 1) / TPB;

    mps_chain_kernel<<<grid, TPB>>>(x, core0, cores_mid, coreN, out, B);
}

// round 3
// speedup vs baseline: 1.0986x; 1.0986x over previous
#include <cuda_runtime.h>
#include <cstdint>

// CachedMPS on GB300, R2->R3: 2 batch rows per thread to halve LDS wavefronts
// per FMA (R2 was L1/shared-bound: LDS=2x fma cost). Chain math unchanged:
// normalization-free homogeneous chain, periodic range-control rescale,
// eps-free final unit-normalize.

#define DEV_INLINE __device__ __forceinline__

static constexpr int D    = 32;
static constexpr int L    = 256;
static constexpr int NMID = 254;   // L - 2
static constexpr int C    = 10;
static constexpr int TPB  = 128;
static constexpr int R    = 2;     // batch rows per thread
static constexpr float HALF_PI = 1.57079632679489662f;

// ---------------- f32x2 helpers (sm_103a packed fp32) ----------------
DEV_INLINE unsigned long long pack2(float x) {
    unsigned long long r;
    asm("mov.b64 %0, {%1, %1};" : "=l"(r) : "f"(x));
    return r;
}
DEV_INLINE void unpack2(unsigned long long v, float& lo, float& hi) {
    asm("mov.b64 {%0, %1}, %2;" : "=f"(lo), "=f"(hi) : "l"(v));
}
DEV_INLINE void ffma2(unsigned long long& d, unsigned long long a, unsigned long long b) {
    asm("fma.rn.f32x2 %0, %1, %2, %0;" : "+l"(d) : "l"(a), "l"(b));
}

// ---------------- cp.async 16B ----------------
DEV_INLINE void cp16(unsigned dst_smem, const void* src) {
    asm volatile("cp.async.cg.shared.global [%0], [%1], 16;"
                 :: "r"(dst_smem), "l"(src));
}
DEV_INLINE void cp_commit() { asm volatile("cp.async.commit_group;"); }
DEV_INLINE void cp_wait0()  { asm volatile("cp.async.wait_group 0;" ::: "memory"); }

__global__ void __launch_bounds__(TPB)
mps_chain_kernel(const float* __restrict__ x,
                 const float* __restrict__ core0,
                 const float* __restrict__ cores_mid,
                 const float* __restrict__ coreN,
                 float* __restrict__ out,
                 int B)
{
    __shared__ __align__(16) unsigned long long sA[2][1024];  // 2 x 8KB tiles

    const int tid  = threadIdx.x;
    const int half = B / R;                       // 16384
    const int b0   = blockIdx.x * TPB + tid;      // row 0
    const int b1   = b0 + half;                   // row 1
    const bool act0 = (b0 < B);
    const bool act1 = (b1 < B);
    const int r0i = act0 ? b0 : 0;
    const int r1i = act1 ? b1 : 0;

    unsigned sbase0 = (unsigned)__cvta_generic_to_shared(&sA[0][0]);
    unsigned sbase1 = (unsigned)__cvta_generic_to_shared(&sA[1][0]);

    // ---- prefetch step 0 tile (512 x 16B across 128 threads = 4 each) ----
    {
        const float* g = cores_mid;
        #pragma unroll
        for (int i = 0; i < 4; i++) {
            int idx = tid + i * TPB;
            cp16(sbase0 + idx * 16, g + idx * 4);
        }
        cp_commit();
    }

    const float* xr0 = x + (size_t)r0i * L;
    const float* xr1 = x + (size_t)r1i * L;

    // ---- init M for both rows: M0 = c*core0[0,:] + s*core0[1,:] ----
    float m0[D], m1[D];
    {
        float s, c;
        __sincosf(HALF_PI * xr0[0], &s, &c);
        #pragma unroll
        for (int d = 0; d < D; d++) m0[d] = c * core0[d] + s * core0[D + d];
        __sincosf(HALF_PI * xr1[0], &s, &c);
        #pragma unroll
        for (int d = 0; d < D; d++) m1[d] = c * core0[d] + s * core0[D + d];
    }

    cp_wait0();
    __syncthreads();

    // ---- main sequential chain ----
    for (int l = 0; l < NMID; l++) {
        const int cur = l & 1;

        if (l + 1 < NMID) {
            const float* g = cores_mid + (size_t)(l + 1) * 2048;
            unsigned sb = (cur == 0) ? sbase1 : sbase0;
            #pragma unroll
            for (int i = 0; i < 4; i++) {
                int idx = tid + i * TPB;
                cp16(sb + idx * 16, g + idx * 4);
            }
            cp_commit();
        }

        float sv0, cv0, sv1, cv1;
        __sincosf(HALF_PI * xr0[l + 1], &sv0, &cv0);
        __sincosf(HALF_PI * xr1[l + 1], &sv1, &cv1);

        unsigned long long acc0[16], acc1[16];
        #pragma unroll
        for (int j = 0; j < 16; j++) { acc0[j] = 0ull; acc1[j] = 0ull; }

        const unsigned long long* A0 = &sA[cur][0];
        const unsigned long long* A1 = &sA[cur][512];

        #pragma unroll
        for (int a = 0; a < D; a++) {
            const float ma0 = m0[a];
            const float ma1 = m1[a];
            const unsigned long long cm0 = pack2(cv0 * ma0);
            const unsigned long long sm0 = pack2(sv0 * ma0);
            const unsigned long long cm1 = pack2(cv1 * ma1);
            const unsigned long long sm1 = pack2(sv1 * ma1);
            const ulonglong2* ra = reinterpret_cast<const ulonglong2*>(A0 + a * 16);
            const ulonglong2* rb = reinterpret_cast<const ulonglong2*>(A1 + a * 16);
            #pragma unroll
            for (int q = 0; q < 8; q++) {
                ulonglong2 v0 = ra[q];                   // LDS.128 broadcast
                ffma2(acc0[2 * q],     cm0, v0.x);
                ffma2(acc0[2 * q + 1], cm0, v0.y);
                ffma2(acc1[2 * q],     cm1, v0.x);
                ffma2(acc1[2 * q + 1], cm1, v0.y);
                ulonglong2 v1 = rb[q];
                ffma2(acc0[2 * q],     sm0, v1.x);
                ffma2(acc0[2 * q + 1], sm0, v1.y);
                ffma2(acc1[2 * q],     sm1, v1.x);
                ffma2(acc1[2 * q + 1], sm1, v1.y);
            }
        }

        #pragma unroll
        for (int j = 0; j < 16; j++) {
            unpack2(acc0[j], m0[2 * j], m0[2 * j + 1]);
            unpack2(acc1[j], m1[2 * j], m1[2 * j + 1]);
        }

        // range control every 32 steps (scale-invariant chain)
        if ((l & 31) == 31) {
            float ss0 = 0.f, ss1 = 0.f;
            #pragma unroll
            for (int d = 0; d < D; d++) { ss0 += m0[d] * m0[d]; ss1 += m1[d] * m1[d]; }
            const float q0 = rsqrtf(ss0);
            const float q1 = rsqrtf(ss1);
            #pragma unroll
            for (int d = 0; d < D; d++) { m0[d] *= q0; m1[d] *= q1; }
        }

        cp_wait0();
        __syncthreads();
    }

    // ---- readout (eps-free final unit-normalize; see R1 post-mortem) ----
    if (act0) {
        float ss = 0.f;
        #pragma unroll
        for (int d = 0; d < D; d++) ss += m0[d] * m0[d];
        const float inv = rsqrtf(ss);
        float sL, cL;
        __sincosf(HALF_PI * xr0[L - 1], &sL, &cL);
        float lg[C];
        #pragma unroll
        for (int c = 0; c < C; c++) lg[c] = 0.f;
        #pragma unroll
        for (int a = 0; a < D; a++) {
            const float ma = m0[a];
            #pragma unroll
            for (int c = 0; c < C; c++) {
                const float w = cL * coreN[a * C + c] + sL * coreN[D * C + a * C + c];
                lg[c] += ma * w;
            }
        }
        #pragma unroll
        for (int c = 0; c < C; c++)
            out[(size_t)b0 * C + c] = lg[c] * inv;
    }
    if (act1) {
        float ss = 0.f;
        #pragma unroll
        for (int d = 0; d < D; d++) ss += m1[d] * m1[d];
        const float inv = rsqrtf(ss);
        float sL, cL;
        __sincosf(HALF_PI * xr1[L - 1], &sL, &cL);
        float lg[C];
        #pragma unroll
        for (int c = 0; c < C; c++) lg[c] = 0.f;
        #pragma unroll
        for (int a = 0; a < D; a++) {
            const float ma = m1[a];
            #pragma unroll
            for (int c = 0; c < C; c++) {
                const float w = cL * coreN[a * C + c] + sL * coreN[D * C + a * C + c];
                lg[c] += ma * w;
            }
        }
        #pragma unroll
        for (int c = 0; c < C; c++)
            out[(size_t)b1 * C + c] = lg[c] * inv;
    }
}

extern "C" void kernel_launch(void* const* d_in, const int* in_sizes, int n_in,
                              void* d_out, int out_size)
{
    const float* x         = (const float*)d_in[0];
    const float* core0     = (const float*)d_in[1];
    const float* cores_mid = (const float*)d_in[2];
    const float* coreN     = (const float*)d_in[3];
    float* out = (float*)d_out;

    const int B = in_sizes[0] / L;
    const int rows_per_block = TPB * R;
    const int grid = (B + rows_per_block - 1) / rows_per_block;   // 128 for B=32768

    mps_chain_kernel<<<grid, TPB>>>(x, core0, cores_mid, coreN, out, B);
}

// round 5
// speedup vs baseline: 1.9576x; 1.7819x over previous
#include <cuda_runtime.h>
#include <cstdint>

// CachedMPS on GB300 via legacy mma.sync (HMMA) tf32 2-split.
// (tcgen05 unavailable: harness PTX target is sm_103 without the 'a' suffix.)
//
//   step:  Mnew[32,32] = [cv*M | sv*M][32,64] x W_l[64,32]   per warp
//   split: hi*Whi + hi*Wlo + lo*Whi  (3 tf32 mma terms, f32 accum)
//
// Per-step L2-normalize removed (scale-invariant homogeneous chain); rsqrt of
// the current M folded into cv/sv each step (range control); eps-free final
// unit-normalize (reference's final M has norm ~1, so its eps is negligible).

#define DEV_INLINE __device__ __forceinline__

static constexpr int D    = 32;
static constexpr int L    = 256;
static constexpr int NMID = 254;
static constexpr int C    = 10;
static constexpr int TPB  = 256;              // 8 warps
static constexpr int ROWS_PER_WARP = 32;      // 2 m-tiles
static constexpr int ROWS_PER_CTA  = 256;
static constexpr float HALF_PI = 1.57079632679489662f;

// W scratch: [NMID][2][2048] floats — [hi|lo], fragment-native order (see prep_B)
__device__ float g_Bt[(size_t)NMID * 4096];

DEV_INLINE unsigned f2tf32(float v) {
    unsigned r; asm("cvt.rna.tf32.f32 %0, %1;" : "=r"(r) : "f"(v)); return r;
}
DEV_INLINE unsigned smem_u32(const void* p) {
    unsigned r;
    asm("{ .reg .u64 t; cvta.to.shared.u64 t, %1; cvt.u32.u64 %0, t; }" : "=r"(r) : "l"(p));
    return r;
}
DEV_INLINE void cp16(unsigned dst, const void* src) {
    asm volatile("cp.async.cg.shared.global [%0], [%1], 16;" :: "r"(dst), "l"(src));
}
DEV_INLINE void cp_commit() { asm volatile("cp.async.commit_group;"); }
DEV_INLINE void cp_wait0()  { asm volatile("cp.async.wait_group 0;" ::: "memory"); }

// m16n8k8 row.col f32.tf32.tf32.f32, accumulate in place
DEV_INLINE void mma8(float* c, const unsigned* a, unsigned b0, unsigned b1) {
    asm("mma.sync.aligned.m16n8k8.row.col.f32.tf32.tf32.f32 "
        "{%0,%1,%2,%3}, {%4,%5,%6,%7}, {%8,%9}, {%0,%1,%2,%3};"
        : "+f"(c[0]), "+f"(c[1]), "+f"(c[2]), "+f"(c[3])
        : "r"(a[0]), "r"(a[1]), "r"(a[2]), "r"(a[3]), "r"(b0), "r"(b1));
}

// ---- prep: write W hi/lo in B-fragment-native order ----
// slot (within 2048-float half): i = ((t*2+jp)*32 + lane)*4 + s
//   t=k-tile(0..7 packed as tp=t*2+jp? no: tp=i>>7, t=tp>>1, jp=tp&1)
//   j = 2*jp + (s>>1), reg = s&1, q=lane&3, g=lane>>2
//   value = W[k = 8t + q + 4*reg][col = 8j + g]
// so a warp's B-frag pair for (t, j, j+1) is one conflict-free LDS.128.
__global__ void prep_B(const float* __restrict__ cores_mid) {
    const int l = blockIdx.x;
    const float* src = cores_mid + (size_t)l * 2048;   // [f][a][c]
    float* dst = g_Bt + (size_t)l * 4096;
    for (int i = threadIdx.x; i < 2048; i += blockDim.x) {
        const int s = i & 3, lane = (i >> 2) & 31, tp = i >> 7;
        const int t = tp >> 1, jp = tp & 1;
        const int j = 2 * jp + (s >> 1), reg = s & 1;
        const int q = lane & 3, g = lane >> 2;
        const int k = 8 * t + q + 4 * reg;
        const int c = 8 * j + g;
        const float v = src[(k >> 5) * 1024 + (k & 31) * 32 + c];
        const unsigned hi = f2tf32(v);
        dst[i]        = __uint_as_float(hi);
        dst[2048 + i] = f2tf32(v - __uint_as_float(hi)) == 0u ? 0.f
                      : __uint_as_float(f2tf32(v - __uint_as_float(hi)));
    }
}

__global__ void __launch_bounds__(TPB)
mps_hmma_kernel(const float* __restrict__ x,
                const float* __restrict__ core0,
                const float* __restrict__ coreN,
                float* __restrict__ out, int B)
{
    __shared__ __align__(16) float sW[2][4096];   // 2 stages x (hi 8KB | lo 8KB)

    const int tid  = threadIdx.x;
    const int lane = tid & 31;
    const int w    = tid >> 5;
    const int q    = lane & 3;
    const int g    = lane >> 2;
    const int rowbase = blockIdx.x * ROWS_PER_CTA + w * ROWS_PER_WARP;

    // lane's 4 rows: rid = mt*2 + rowsel -> row = rowbase + mt*16 + g + 8*rowsel
    int rows[4];
    #pragma unroll
    for (int rid = 0; rid < 4; rid++) {
        int r = rowbase + (rid >> 1) * 16 + g + (rid & 1) * 8;
        rows[rid] = (r < B) ? r : (B - 1);
    }

    // prefetch step-0 W (16KB): 1024 chunks / 256 threads
    {
        const float* gsrc = g_Bt;
        #pragma unroll
        for (int i = 0; i < 4; i++) {
            int idx = tid + i * TPB;
            cp16(smem_u32(&sW[0][0]) + idx * 16, gsrc + idx * 4);
        }
        cp_commit();
    }

    // ---- init acc = M0 (mma c-fragment layout) ----
    // acc[mt][4j + 2*rowsel + p]: row = g+8*rowsel (+16mt), col = 8j + 2q + p
    float acc[2][16];
    #pragma unroll
    for (int rid = 0; rid < 4; rid++) {
        float s0, c0;
        __sincosf(HALF_PI * __ldg(x + (size_t)rows[rid] * L), &s0, &c0);
        const int mt = rid >> 1, rowsel = rid & 1;
        #pragma unroll
        for (int j = 0; j < 4; j++)
            #pragma unroll
            for (int p = 0; p < 2; p++) {
                const int col = 8 * j + 2 * q + p;
                acc[mt][4 * j + 2 * rowsel + p] =
                    c0 * core0[col] + s0 * core0[32 + col];
            }
    }

    // ---- chain: 254 tensor-core steps ----
    for (int l = 0; l < NMID; l++) {
        cp_wait0();
        __syncthreads();                     // stage l&1 ready; prev reads done

        if (l + 1 < NMID) {                  // prefetch next stage
            const float* gsrc = g_Bt + (size_t)(l + 1) * 4096;
            const unsigned sb = smem_u32(&sW[(l + 1) & 1][0]);
            #pragma unroll
            for (int i = 0; i < 4; i++) {
                int idx = tid + i * TPB;
                cp16(sb + idx * 16, gsrc + idx * 4);
            }
            cp_commit();
        }

        // row norms (quad-reduce) and cv/sv with rsqrt folded in
        float cv[4], sv[4];
        #pragma unroll
        for (int rid = 0; rid < 4; rid++) {
            const int mt = rid >> 1, rowsel = rid & 1;
            float ss = 0.f;
            #pragma unroll
            for (int j = 0; j < 4; j++) {
                float v0 = acc[mt][4 * j + 2 * rowsel];
                float v1 = acc[mt][4 * j + 2 * rowsel + 1];
                ss += v0 * v0 + v1 * v1;
            }
            ss += __shfl_xor_sync(0xffffffffu, ss, 1);
            ss += __shfl_xor_sync(0xffffffffu, ss, 2);
            const float rs = rsqrtf(ss);
            float sn, cs;
            __sincosf(HALF_PI * __ldg(x + (size_t)rows[rid] * L + (l + 1)), &sn, &cs);
            cv[rid] = cs * rs;
            sv[rid] = sn * rs;
        }

        const float* Whi = &sW[l & 1][0];
        const float* Wlo = &sW[l & 1][2048];

        float na[2][16];
        #pragma unroll
        for (int mt = 0; mt < 2; mt++)
            #pragma unroll
            for (int k = 0; k < 16; k++) na[mt][k] = 0.f;

        #pragma unroll
        for (int tt = 0; tt < 4; tt++) {
            // B fragments: th=0 -> k-tile tt (cv half), th=1 -> tt+4 (sv half)
            float bh[2][2][4], bl[2][2][4];
            #pragma unroll
            for (int th = 0; th < 2; th++) {
                const int t = tt + 4 * th;
                #pragma unroll
                for (int jp = 0; jp < 2; jp++) {
                    const int fi = ((t * 2 + jp) * 32 + lane) * 4;
                    const float4 vh = *reinterpret_cast<const float4*>(Whi + fi);
                    const float4 vl = *reinterpret_cast<const float4*>(Wlo + fi);
                    bh[th][jp][0] = vh.x; bh[th][jp][1] = vh.y;
                    bh[th][jp][2] = vh.z; bh[th][jp][3] = vh.w;
                    bl[th][jp][0] = vl.x; bl[th][jp][1] = vl.y;
                    bl[th][jp][2] = vl.z; bl[th][jp][3] = vl.w;
                }
            }

            #pragma unroll
            for (int mt = 0; mt < 2; mt++) {
                // gather A raw values from acc via shuffles:
                // a-reg i: row g+8*(i&1), k-col 8tt + q + 4*(i>>1)
                float av[4];
                #pragma unroll
                for (int i = 0; i < 4; i++) {
                    const int rowsel = i & 1, khalf = i >> 1;
                    const int srcLane = 4 * g + (q >> 1) + 2 * khalf;
                    const float v0 = __shfl_sync(0xffffffffu,
                                                 acc[mt][4 * tt + 2 * rowsel], srcLane);
                    const float v1 = __shfl_sync(0xffffffffu,
                                                 acc[mt][4 * tt + 2 * rowsel + 1], srcLane);
                    av[i] = (q & 1) ? v1 : v0;
                }
                // build tf32 hi/lo frags for cv- and sv-scaled halves
                unsigned cahi[4], calo[4], sahi[4], salo[4];
                #pragma unroll
                for (int i = 0; i < 4; i++) {
                    const int rid = mt * 2 + (i & 1);
                    const float vc = av[i] * cv[rid];
                    cahi[i] = f2tf32(vc);
                    calo[i] = f2tf32(vc - __uint_as_float(cahi[i]));
                    const float vs = av[i] * sv[rid];
                    sahi[i] = f2tf32(vs);
                    salo[i] = f2tf32(vs - __uint_as_float(sahi[i]));
                }
                #pragma unroll
                for (int th = 0; th < 2; th++) {
                    const unsigned* ah = th ? sahi : cahi;
                    const unsigned* al = th ? salo : calo;
                    #pragma unroll
                    for (int j = 0; j < 4; j++) {
                        const int jp = j >> 1, e = (j & 1) * 2;
                        const unsigned b0h = __float_as_uint(bh[th][jp][e]);
                        const unsigned b1h = __float_as_uint(bh[th][jp][e + 1]);
                        const unsigned b0l = __float_as_uint(bl[th][jp][e]);
                        const unsigned b1l = __float_as_uint(bl[th][jp][e + 1]);
                        mma8(&na[mt][4 * j], ah, b0h, b1h);   // hi*Whi
                        mma8(&na[mt][4 * j], ah, b0l, b1l);   // hi*Wlo
                        mma8(&na[mt][4 * j], al, b0h, b1h);   // lo*Whi
                    }
                }
            }
        }

        #pragma unroll
        for (int mt = 0; mt < 2; mt++)
            #pragma unroll
            for (int k = 0; k < 16; k++) acc[mt][k] = na[mt][k];
    }

    // ---- readout: eps-free unit normalize + coreN contraction ----
    #pragma unroll
    for (int rid = 0; rid < 4; rid++) {
        const int mt = rid >> 1, rowsel = rid & 1;
        const int row = rowbase + mt * 16 + g + 8 * rowsel;

        float ss = 0.f;
        #pragma unroll
        for (int j = 0; j < 4; j++) {
            float v0 = acc[mt][4 * j + 2 * rowsel];
            float v1 = acc[mt][4 * j + 2 * rowsel + 1];
            ss += v0 * v0 + v1 * v1;
        }
        ss += __shfl_xor_sync(0xffffffffu, ss, 1);
        ss += __shfl_xor_sync(0xffffffffu, ss, 2);
        const float inv = rsqrtf(ss);           // NO eps (R1 lesson)

        float sL, cL;
        __sincosf(HALF_PI * __ldg(x + (size_t)rows[rid] * L + (L - 1)), &sL, &cL);

        float lg[C];
        #pragma unroll
        for (int cc = 0; cc < C; cc++) lg[cc] = 0.f;
        #pragma unroll
        for (int j = 0; j < 4; j++)
            #pragma unroll
            for (int p = 0; p < 2; p++) {
                const int col = 8 * j + 2 * q + p;
                const float m = acc[mt][4 * j + 2 * rowsel + p];
                #pragma unroll
                for (int cc = 0; cc < C; cc++) {
                    const float wv = cL * coreN[col * C + cc]
                                   + sL * coreN[D * C + col * C + cc];
                    lg[cc] += m * wv;
                }
            }
        #pragma unroll
        for (int cc = 0; cc < C; cc++) {
            lg[cc] += __shfl_xor_sync(0xffffffffu, lg[cc], 1);
            lg[cc] += __shfl_xor_sync(0xffffffffu, lg[cc], 2);
        }
        if (q == 0 && row < B) {
            #pragma unroll
            for (int cc = 0; cc < C; cc++)
                out[(size_t)row * C + cc] = lg[cc] * inv;
        }
    }
}

extern "C" void kernel_launch(void* const* d_in, const int* in_sizes, int n_in,
                              void* d_out, int out_size)
{
    const float* x         = (const float*)d_in[0];
    const float* core0     = (const float*)d_in[1];
    const float* cores_mid = (const float*)d_in[2];
    const float* coreN     = (const float*)d_in[3];
    float* out = (float*)d_out;

    const int B = in_sizes[0] / L;
    const int grid = (B + ROWS_PER_CTA - 1) / ROWS_PER_CTA;   // 128

    prep_B<<<NMID, 256>>>(cores_mid);
    mps_hmma_kernel<<<grid, TPB>>>(x, core0, coreN, out, B);
}